// round 9
// baseline (speedup 1.0000x reference)
#include <cuda_runtime.h>
#include <cuda_bf16.h>
#include <cstdint>

#define B_ 4
#define N_ 4096
#define C_ 256
#define M_ (B_ * N_)

#define ROWB 144      // bytes per SMEM row (64 bf16 = 128B + 16B pad)

// SMEM layout (dynamic) for k_gemm:
#define SM_AHI 0
#define SM_ALO 18432
#define SM_B0  36864            // buffer 0: hi at +0, lo at +36864
#define BUFSZ  73728
#define SM_TOTAL (36864 + 2 * BUFSZ)   // 184320

#define GRID_GEMM 128
#define THREADS 512
#define YSTRIDE 260             // fp32 words per staged y row (padded)

// ---------------- device scratch ----------------
__device__ __nv_bfloat16 g_Bhi[C_ * C_];   // W^T hi, [n][k]
__device__ __nv_bfloat16 g_Blo[C_ * C_];   // W^T lo, [n][k]
__device__ float g_sum[B_ * C_];
__device__ float g_sumsq[B_ * C_];
__device__ unsigned g_bar;                 // grid barrier (zeroed by k_prep2)

__device__ __forceinline__ uint32_t smem_u32(const void* p) {
    uint32_t a;
    asm("{ .reg .u64 t; cvta.to.shared.u64 t, %1; cvt.u32.u64 %0, t; }" : "=r"(a) : "l"(p));
    return a;
}
__device__ __forceinline__ void cp16(uint32_t dst, const void* src) {
    asm volatile("cp.async.cg.shared.global [%0], [%1], 16;" :: "r"(dst), "l"(src));
}
__device__ __forceinline__ void cp_commit() {
    asm volatile("cp.async.commit_group;" ::: "memory");
}
template <int N> __device__ __forceinline__ void cp_wait() {
    asm volatile("cp.async.wait_group %0;" :: "n"(N) : "memory");
}
__device__ __forceinline__ void ldmx4(uint32_t* r, uint32_t addr) {
    asm volatile("ldmatrix.sync.aligned.m8n8.x4.shared.b16 {%0,%1,%2,%3}, [%4];"
                 : "=r"(r[0]), "=r"(r[1]), "=r"(r[2]), "=r"(r[3]) : "r"(addr));
}
__device__ __forceinline__ void ldmx2(uint32_t* r, uint32_t addr) {
    asm volatile("ldmatrix.sync.aligned.m8n8.x2.shared.b16 {%0,%1}, [%2];"
                 : "=r"(r[0]), "=r"(r[1]) : "r"(addr));
}
__device__ __forceinline__ void mma16816(float* c, const uint32_t* a, const uint32_t* b) {
    asm volatile(
        "mma.sync.aligned.m16n8k16.row.col.f32.bf16.bf16.f32 "
        "{%0,%1,%2,%3}, {%4,%5,%6,%7}, {%8,%9}, {%0,%1,%2,%3};"
        : "+f"(c[0]), "+f"(c[1]), "+f"(c[2]), "+f"(c[3])
        : "r"(a[0]), "r"(a[1]), "r"(a[2]), "r"(a[3]), "r"(b[0]), "r"(b[1]));
}

// ---------------------------------------------------------------------------
// K1: W row i = Wv[i,:] @ Wo  (one CTA per row, full k-reduction, MLP-32).
// Emits transposed bf16 hi/lo directly; CTA 0 zeroes stats + barrier.
// (Per-channel bias cancels exactly through the N-axis LayerNorm -> dropped.)
// ---------------------------------------------------------------------------
__global__ __launch_bounds__(256) void k_prep2(const float* __restrict__ Wv,
                                               const float* __restrict__ Wo) {
    __shared__ float s_wv[C_];
    int t = threadIdx.x;
    int i = blockIdx.x;                  // W row index (= k index of B operand)
    s_wv[t] = Wv[i * C_ + t];
    __syncthreads();

    float acc = 0.f;
    for (int m0 = 0; m0 < C_; m0 += 32) {
        float w[32];
        #pragma unroll
        for (int u = 0; u < 32; u++) w[u] = Wo[(m0 + u) * C_ + t];
        #pragma unroll
        for (int u = 0; u < 32; u++) acc += s_wv[m0 + u] * w[u];
    }
    __nv_bfloat16 h = __float2bfloat16(acc);
    g_Bhi[t * C_ + i] = h;                               // B operand = W^T
    g_Blo[t * C_ + i] = __float2bfloat16(acc - __bfloat162float(h));

    if (i == 0) {
        float4 z = make_float4(0.f, 0.f, 0.f, 0.f);
        *(float4*)&g_sum[t * 4] = z;
        *(float4*)&g_sumsq[t * 4] = z;
        if (t == 0) g_bar = 0u;
    }
}

// ---------------------------------------------------------------------------
// K2: y = X @ W (split-bf16 HMMA), 512 threads (16 warps, 4x4 warp grid,
// warp tile 32x64). Fused stats atomics -> grid barrier (overlapped with smem
// y staging) -> coalesced LN+relu+residual apply.
// ---------------------------------------------------------------------------
__global__ __launch_bounds__(THREADS, 1) void k_gemm(const float* __restrict__ X,
                                                     const float* __restrict__ ls,
                                                     const float* __restrict__ lb,
                                                     float* __restrict__ out) {
    extern __shared__ char smem[];
    uint32_t sb = smem_u32(smem);
    int t = threadIdx.x, wid = t >> 5, lane = t & 31;
    int warpM = wid >> 2, warpN = wid & 3;     // 4 x 4
    int m0 = blockIdx.x * 128;
    int q = t & 3, rr = t >> 2;                // loader coords: rr 0..127

    float acc[2][8][4];
    #pragma unroll
    for (int i = 0; i < 2; i++)
        #pragma unroll
        for (int j = 0; j < 8; j++)
            #pragma unroll
            for (int r = 0; r < 4; r++) acc[i][j][r] = 0.f;

    uint32_t aBase = sb + SM_AHI +
        (warpM * 32 + ((lane >> 3) & 1) * 8 + (lane & 7)) * ROWB + (lane >> 4) * 16;

    auto issueB = [&](int c, int buf) {
        uint32_t bhi = sb + SM_B0 + buf * BUFSZ;
        uint32_t blo = bhi + 36864;
        const char* shi = (const char*)g_Bhi + c * 128 + q * 32;
        const char* slo = (const char*)g_Blo + c * 128 + q * 32;
        #pragma unroll
        for (int it = 0; it < 2; it++) {
            int row = it * 128 + rr;
            uint32_t d = row * ROWB + q * 32;
            const char* sh = shi + (size_t)row * 512;
            const char* sl = slo + (size_t)row * 512;
            cp16(bhi + d, sh);       cp16(bhi + d + 16, sh + 16);
            cp16(blo + d, sl);       cp16(blo + d + 16, sl + 16);
        }
        cp_commit();
    };
    float areg[16];
    auto loadA = [&](int c) {
        const float* src = X + (size_t)(m0 + rr) * C_ + c * 64 + q * 16;
        #pragma unroll
        for (int i = 0; i < 4; i++)
            *(float4*)&areg[i * 4] = *(const float4*)(src + i * 4);
    };
    auto storeA = [&]() {
        __nv_bfloat16 h[16], l[16];
        #pragma unroll
        for (int i = 0; i < 16; i++) {
            float v = areg[i];
            h[i] = __float2bfloat16(v);
            l[i] = __float2bfloat16(v - __bfloat162float(h[i]));
        }
        char* dh = smem + SM_AHI + rr * ROWB + q * 32;
        char* dl = smem + SM_ALO + rr * ROWB + q * 32;
        *(uint4*)dh = *(uint4*)&h[0]; *(uint4*)(dh + 16) = *(uint4*)&h[8];
        *(uint4*)dl = *(uint4*)&l[0]; *(uint4*)(dl + 16) = *(uint4*)&l[8];
    };

    issueB(0, 0);
    loadA(0);

    for (int c = 0; c < 4; c++) {
        if (c < 3) issueB(c + 1, (c + 1) & 1);
        storeA();
        if (c < 3) cp_wait<1>(); else cp_wait<0>();
        __syncthreads();
        if (c < 3) loadA(c + 1);           // DRAM latency hides under MMAs

        uint32_t bBase = sb + SM_B0 + (c & 1) * BUFSZ +
            (warpN * 64 + (lane & 7)) * ROWB + ((lane >> 3) & 1) * 16;
        #pragma unroll
        for (int ks = 0; ks < 4; ks++) {
            uint32_t ah[2][4], al[2][4];
            #pragma unroll
            for (int ms = 0; ms < 2; ms++) {
                uint32_t addr = aBase + ms * (16 * ROWB) + ks * 32;
                ldmx4(ah[ms], addr);
                ldmx4(al[ms], addr + (SM_ALO - SM_AHI));
            }
            #pragma unroll
            for (int ns = 0; ns < 8; ns++) {
                uint32_t bh[2], bl[2];
                uint32_t addr = bBase + ns * (8 * ROWB) + ks * 32;
                ldmx2(bh, addr);
                ldmx2(bl, addr + 36864);
                #pragma unroll
                for (int ms = 0; ms < 2; ms++) {
                    mma16816(acc[ms][ns], ah[ms], bh);
                    mma16816(acc[ms][ns], ah[ms], bl);
                    mma16816(acc[ms][ns], al[ms], bh);
                }
            }
        }
        __syncthreads();
    }

    // ---- column stats from registers, atomics into g_sum/g_sumsq ----
    int b = m0 >> 12;
    int gid = lane >> 2, tig = lane & 3;
    #pragma unroll
    for (int ns = 0; ns < 8; ns++) {
        float s0 = 0.f, s1 = 0.f, q0 = 0.f, q1 = 0.f;
        #pragma unroll
        for (int ms = 0; ms < 2; ms++)
            #pragma unroll
            for (int half = 0; half < 2; half++) {
                float v0 = acc[ms][ns][half * 2 + 0];
                float v1 = acc[ms][ns][half * 2 + 1];
                s0 += v0; q0 += v0 * v0;
                s1 += v1; q1 += v1 * v1;
            }
        #pragma unroll
        for (int off = 4; off < 32; off <<= 1) {
            s0 += __shfl_xor_sync(0xFFFFFFFFu, s0, off);
            s1 += __shfl_xor_sync(0xFFFFFFFFu, s1, off);
            q0 += __shfl_xor_sync(0xFFFFFFFFu, q0, off);
            q1 += __shfl_xor_sync(0xFFFFFFFFu, q1, off);
        }
        if (gid == 0) {
            int col = warpN * 64 + ns * 8 + tig * 2;
            atomicAdd(&g_sum[b * C_ + col],     s0);
            atomicAdd(&g_sum[b * C_ + col + 1], s1);
            atomicAdd(&g_sumsq[b * C_ + col],     q0);
            atomicAdd(&g_sumsq[b * C_ + col + 1], q1);
        }
    }

    // ---- arrive, then stage y into smem while other CTAs drain ----
    __threadfence();
    __syncthreads();
    if (t == 0) atomicAdd(&g_bar, 1u);

    float* ys = (float*)smem;               // 128 x YSTRIDE fp32 (133120 B)
    #pragma unroll
    for (int ms = 0; ms < 2; ms++)
        #pragma unroll
        for (int half = 0; half < 2; half++) {
            int rl = warpM * 32 + ms * 16 + half * 8 + gid;
            #pragma unroll
            for (int ns = 0; ns < 8; ns++) {
                int col = warpN * 64 + ns * 8 + tig * 2;
                ys[rl * YSTRIDE + col]     = acc[ms][ns][half * 2 + 0];
                ys[rl * YSTRIDE + col + 1] = acc[ms][ns][half * 2 + 1];
            }
        }

    __syncthreads();
    if (t == 0) { while (*(volatile unsigned*)&g_bar < GRID_GEMM) { } }
    __syncthreads();

    // ---- per-channel sc/mb ----
    float* sc = ys + 128 * YSTRIDE;         // 256 floats
    float* mb = sc + 256;                   // 256 floats
    if (t < 256) {
        const float inv = 1.f / N_;
        float sm_ = __ldcg(&g_sum[b * C_ + t]);
        float sq_ = __ldcg(&g_sumsq[b * C_ + t]);
        float mu = sm_ * inv;
        float rs = rsqrtf(sq_ * inv - mu * mu + 1e-6f);
        float s = ls[t] * rs;
        sc[t] = s;
        mb[t] = lb[t] - mu * s;
    }
    __syncthreads();

    // ---- coalesced apply: out = relu(y*sc + mb) + X ----
    #pragma unroll 4
    for (int it = 0; it < 16; it++) {
        int slot = it * THREADS + t;        // 8192 float4 slots
        int row = slot >> 6, c4 = slot & 63;
        float4 y = *(float4*)&ys[row * YSTRIDE + c4 * 4];
        float4 s4 = *(float4*)&sc[c4 * 4];
        float4 m4 = *(float4*)&mb[c4 * 4];
        const float* xp = X + (size_t)(m0 + row) * C_ + c4 * 4;
        float4 x = *(const float4*)xp;
        float4 o;
        o.x = fmaxf(y.x * s4.x + m4.x, 0.f) + x.x;
        o.y = fmaxf(y.y * s4.y + m4.y, 0.f) + x.y;
        o.z = fmaxf(y.z * s4.z + m4.z, 0.f) + x.z;
        o.w = fmaxf(y.w * s4.w + m4.w, 0.f) + x.w;
        *(float4*)(out + (size_t)(m0 + row) * C_ + c4 * 4) = o;
    }
}

// ---------------------------------------------------------------------------
extern "C" void kernel_launch(void* const* d_in, const int* in_sizes, int n_in,
                              void* d_out, int out_size) {
    // order: inputs, mask, Wq, bq, Wk, bk, Wv, bv, Wo, bo, ln_scale, ln_bias
    const float* X  = (const float*)d_in[0];
    const float* Wv = (const float*)d_in[6];
    const float* Wo = (const float*)d_in[8];
    const float* ls = (const float*)d_in[10];
    const float* lb = (const float*)d_in[11];
    float* out = (float*)d_out;

    cudaFuncSetAttribute(k_gemm, cudaFuncAttributeMaxDynamicSharedMemorySize,
                         SM_TOTAL);

    k_prep2<<<C_, 256>>>(Wv, Wo);
    k_gemm<<<GRID_GEMM, THREADS, SM_TOTAL>>>(X, ls, lb, out);
}

// round 10
// speedup vs baseline: 1.3498x; 1.3498x over previous
#include <cuda_runtime.h>
#include <cuda_fp16.h>
#include <cstdint>

#define B_ 4
#define N_ 4096
#define C_ 256
#define M_ (B_ * N_)

#define ROWB 144      // bytes per SMEM row (64 fp16 = 128B + 16B pad)

// SMEM layout (dynamic) for k_gemm mainloop:
#define SM_A   0                       // 128 rows x 144B = 18432
#define SM_B0  18432                   // double-buffered B: 256 rows x 144B
#define BUFSZ  36864
// staging phase reuses smem: 128*260*4 + 2*1024 = 135168
#define SM_TOTAL 135168

#define GRID_GEMM 128
#define THREADS 512
#define YSTRIDE 260             // fp32 words per staged y row (padded)

// ---------------- device scratch ----------------
__device__ __half g_B[C_ * C_];            // W^T fp16, [n][k]
__device__ float g_sum[B_ * C_];
__device__ float g_sumsq[B_ * C_];
__device__ unsigned g_bar;                 // grid barrier (zeroed by k_prep2)

__device__ __forceinline__ uint32_t smem_u32(const void* p) {
    uint32_t a;
    asm("{ .reg .u64 t; cvta.to.shared.u64 t, %1; cvt.u32.u64 %0, t; }" : "=r"(a) : "l"(p));
    return a;
}
__device__ __forceinline__ void cp16(uint32_t dst, const void* src) {
    asm volatile("cp.async.cg.shared.global [%0], [%1], 16;" :: "r"(dst), "l"(src));
}
__device__ __forceinline__ void cp_commit() {
    asm volatile("cp.async.commit_group;" ::: "memory");
}
template <int N> __device__ __forceinline__ void cp_wait() {
    asm volatile("cp.async.wait_group %0;" :: "n"(N) : "memory");
}
__device__ __forceinline__ void ldmx4(uint32_t* r, uint32_t addr) {
    asm volatile("ldmatrix.sync.aligned.m8n8.x4.shared.b16 {%0,%1,%2,%3}, [%4];"
                 : "=r"(r[0]), "=r"(r[1]), "=r"(r[2]), "=r"(r[3]) : "r"(addr));
}
__device__ __forceinline__ void ldmx2(uint32_t* r, uint32_t addr) {
    asm volatile("ldmatrix.sync.aligned.m8n8.x2.shared.b16 {%0,%1}, [%2];"
                 : "=r"(r[0]), "=r"(r[1]) : "r"(addr));
}
__device__ __forceinline__ void mma16816(float* c, const uint32_t* a, const uint32_t* b) {
    asm volatile(
        "mma.sync.aligned.m16n8k16.row.col.f32.f16.f16.f32 "
        "{%0,%1,%2,%3}, {%4,%5,%6,%7}, {%8,%9}, {%0,%1,%2,%3};"
        : "+f"(c[0]), "+f"(c[1]), "+f"(c[2]), "+f"(c[3])
        : "r"(a[0]), "r"(a[1]), "r"(a[2]), "r"(a[3]), "r"(b[0]), "r"(b[1]));
}

// ---------------------------------------------------------------------------
// K1: W row i = Wv[i,:] @ Wo (one CTA per row, fp32 reduce, MLP-32).
// Emits transposed fp16 directly; CTA 0 zeroes stats + barrier.
// (Per-channel bias cancels exactly through the N-axis LayerNorm -> dropped.)
// ---------------------------------------------------------------------------
__global__ __launch_bounds__(256) void k_prep2(const float* __restrict__ Wv,
                                               const float* __restrict__ Wo) {
    __shared__ float s_wv[C_];
    int t = threadIdx.x;
    int i = blockIdx.x;                  // W row index (= k index of B operand)
    s_wv[t] = Wv[i * C_ + t];
    __syncthreads();

    float acc = 0.f;
    for (int m0 = 0; m0 < C_; m0 += 32) {
        float w[32];
        #pragma unroll
        for (int u = 0; u < 32; u++) w[u] = Wo[(m0 + u) * C_ + t];
        #pragma unroll
        for (int u = 0; u < 32; u++) acc += s_wv[m0 + u] * w[u];
    }
    g_B[t * C_ + i] = __float2half(acc);                 // B operand = W^T

    if (i == 0) {
        float4 z = make_float4(0.f, 0.f, 0.f, 0.f);
        *(float4*)&g_sum[t * 4] = z;
        *(float4*)&g_sumsq[t * 4] = z;
        if (t == 0) g_bar = 0u;
    }
}

// ---------------------------------------------------------------------------
// K2: y = X @ W (single-pass fp16 HMMA), 512 threads (16 warps, 4x4 grid,
// warp tile 32x64). Fused stats atomics -> grid barrier (overlapped with smem
// y staging) -> coalesced LN+relu+residual apply.
// ---------------------------------------------------------------------------
__global__ __launch_bounds__(THREADS, 1) void k_gemm(const float* __restrict__ X,
                                                     const float* __restrict__ ls,
                                                     const float* __restrict__ lb,
                                                     float* __restrict__ out) {
    extern __shared__ char smem[];
    uint32_t sb = smem_u32(smem);
    int t = threadIdx.x, wid = t >> 5, lane = t & 31;
    int warpM = wid >> 2, warpN = wid & 3;     // 4 x 4
    int m0 = blockIdx.x * 128;
    int q = t & 3, rr = t >> 2;                // loader coords: rr 0..127

    float acc[2][8][4];
    #pragma unroll
    for (int i = 0; i < 2; i++)
        #pragma unroll
        for (int j = 0; j < 8; j++)
            #pragma unroll
            for (int r = 0; r < 4; r++) acc[i][j][r] = 0.f;

    uint32_t aBase = sb + SM_A +
        (warpM * 32 + ((lane >> 3) & 1) * 8 + (lane & 7)) * ROWB + (lane >> 4) * 16;

    auto issueB = [&](int c, int buf) {
        uint32_t bhi = sb + SM_B0 + buf * BUFSZ;
        const char* sh0 = (const char*)g_B + c * 128 + q * 32;
        #pragma unroll
        for (int it = 0; it < 2; it++) {
            int row = it * 128 + rr;
            uint32_t d = row * ROWB + q * 32;
            const char* sh = sh0 + (size_t)row * 512;
            cp16(bhi + d, sh);       cp16(bhi + d + 16, sh + 16);
        }
        cp_commit();
    };
    float areg[16];
    auto loadA = [&](int c) {
        const float* src = X + (size_t)(m0 + rr) * C_ + c * 64 + q * 16;
        #pragma unroll
        for (int i = 0; i < 4; i++)
            *(float4*)&areg[i * 4] = *(const float4*)(src + i * 4);
    };
    auto storeA = [&]() {
        __half h[16];
        #pragma unroll
        for (int i = 0; i < 16; i++) h[i] = __float2half(areg[i]);
        char* dh = smem + SM_A + rr * ROWB + q * 32;
        *(uint4*)dh = *(uint4*)&h[0]; *(uint4*)(dh + 16) = *(uint4*)&h[8];
    };

    issueB(0, 0);
    loadA(0);

    for (int c = 0; c < 4; c++) {
        if (c < 3) issueB(c + 1, (c + 1) & 1);
        storeA();
        if (c < 3) cp_wait<1>(); else cp_wait<0>();
        __syncthreads();
        if (c < 3) loadA(c + 1);           // DRAM latency hides under MMAs

        uint32_t bBase = sb + SM_B0 + (c & 1) * BUFSZ +
            (warpN * 64 + (lane & 7)) * ROWB + ((lane >> 3) & 1) * 16;
        #pragma unroll
        for (int ks = 0; ks < 4; ks++) {
            uint32_t ah[2][4];
            #pragma unroll
            for (int ms = 0; ms < 2; ms++)
                ldmx4(ah[ms], aBase + ms * (16 * ROWB) + ks * 32);
            #pragma unroll
            for (int ns = 0; ns < 8; ns++) {
                uint32_t bh[2];
                ldmx2(bh, bBase + ns * (8 * ROWB) + ks * 32);
                #pragma unroll
                for (int ms = 0; ms < 2; ms++)
                    mma16816(acc[ms][ns], ah[ms], bh);
            }
        }
        __syncthreads();
    }

    // ---- column stats from registers, atomics into g_sum/g_sumsq ----
    int b = m0 >> 12;
    int gid = lane >> 2, tig = lane & 3;
    #pragma unroll
    for (int ns = 0; ns < 8; ns++) {
        float s0 = 0.f, s1 = 0.f, q0 = 0.f, q1 = 0.f;
        #pragma unroll
        for (int ms = 0; ms < 2; ms++)
            #pragma unroll
            for (int half = 0; half < 2; half++) {
                float v0 = acc[ms][ns][half * 2 + 0];
                float v1 = acc[ms][ns][half * 2 + 1];
                s0 += v0; q0 += v0 * v0;
                s1 += v1; q1 += v1 * v1;
            }
        #pragma unroll
        for (int off = 4; off < 32; off <<= 1) {
            s0 += __shfl_xor_sync(0xFFFFFFFFu, s0, off);
            s1 += __shfl_xor_sync(0xFFFFFFFFu, s1, off);
            q0 += __shfl_xor_sync(0xFFFFFFFFu, q0, off);
            q1 += __shfl_xor_sync(0xFFFFFFFFu, q1, off);
        }
        if (gid == 0) {
            int col = warpN * 64 + ns * 8 + tig * 2;
            atomicAdd(&g_sum[b * C_ + col],     s0);
            atomicAdd(&g_sum[b * C_ + col + 1], s1);
            atomicAdd(&g_sumsq[b * C_ + col],     q0);
            atomicAdd(&g_sumsq[b * C_ + col + 1], q1);
        }
    }

    // ---- arrive, then stage y into smem while other CTAs drain ----
    __threadfence();
    __syncthreads();
    if (t == 0) atomicAdd(&g_bar, 1u);

    float* ys = (float*)smem;               // 128 x YSTRIDE fp32 (133120 B)
    #pragma unroll
    for (int ms = 0; ms < 2; ms++)
        #pragma unroll
        for (int half = 0; half < 2; half++) {
            int rl = warpM * 32 + ms * 16 + half * 8 + gid;
            #pragma unroll
            for (int ns = 0; ns < 8; ns++) {
                int col = warpN * 64 + ns * 8 + tig * 2;
                ys[rl * YSTRIDE + col]     = acc[ms][ns][half * 2 + 0];
                ys[rl * YSTRIDE + col + 1] = acc[ms][ns][half * 2 + 1];
            }
        }

    __syncthreads();
    if (t == 0) { while (*(volatile unsigned*)&g_bar < GRID_GEMM) { } }
    __syncthreads();

    // ---- per-channel sc/mb ----
    float* sc = ys + 128 * YSTRIDE;         // 256 floats
    float* mb = sc + 256;                   // 256 floats
    if (t < 256) {
        const float inv = 1.f / N_;
        float sm_ = __ldcg(&g_sum[b * C_ + t]);
        float sq_ = __ldcg(&g_sumsq[b * C_ + t]);
        float mu = sm_ * inv;
        float rs = rsqrtf(sq_ * inv - mu * mu + 1e-6f);
        float s = ls[t] * rs;
        sc[t] = s;
        mb[t] = lb[t] - mu * s;
    }
    __syncthreads();

    // ---- coalesced apply: out = relu(y*sc + mb) + X ----
    #pragma unroll 4
    for (int it = 0; it < 16; it++) {
        int slot = it * THREADS + t;        // 8192 float4 slots
        int row = slot >> 6, c4 = slot & 63;
        float4 y = *(float4*)&ys[row * YSTRIDE + c4 * 4];
        float4 s4 = *(float4*)&sc[c4 * 4];
        float4 m4 = *(float4*)&mb[c4 * 4];
        const float* xp = X + (size_t)(m0 + row) * C_ + c4 * 4;
        float4 x = *(const float4*)xp;
        float4 o;
        o.x = fmaxf(y.x * s4.x + m4.x, 0.f) + x.x;
        o.y = fmaxf(y.y * s4.y + m4.y, 0.f) + x.y;
        o.z = fmaxf(y.z * s4.z + m4.z, 0.f) + x.z;
        o.w = fmaxf(y.w * s4.w + m4.w, 0.f) + x.w;
        *(float4*)(out + (size_t)(m0 + row) * C_ + c4 * 4) = o;
    }
}

// ---------------------------------------------------------------------------
extern "C" void kernel_launch(void* const* d_in, const int* in_sizes, int n_in,
                              void* d_out, int out_size) {
    // order: inputs, mask, Wq, bq, Wk, bk, Wv, bv, Wo, bo, ln_scale, ln_bias
    const float* X  = (const float*)d_in[0];
    const float* Wv = (const float*)d_in[6];
    const float* Wo = (const float*)d_in[8];
    const float* ls = (const float*)d_in[10];
    const float* lb = (const float*)d_in[11];
    float* out = (float*)d_out;

    cudaFuncSetAttribute(k_gemm, cudaFuncAttributeMaxDynamicSharedMemorySize,
                         SM_TOTAL);

    k_prep2<<<C_, 256>>>(Wv, Wo);
    k_gemm<<<GRID_GEMM, THREADS, SM_TOTAL>>>(X, ls, lb, out);
}